// round 6
// baseline (speedup 1.0000x reference)
#include <cuda_runtime.h>
#include <cuda_bf16.h>
#include <cstddef>

#define MAXC   16     // max combos (2*T*B <= 12 here)
#define JSPLIT 8      // target-dimension split
#define MAXN   4096   // max points
#define MAXP   128    // max partial blocks per extras row

__device__ float g_best[MAXC * JSPLIT * MAXN];   // per-chunk min d2 (w2 included)
__device__ int   g_bidx[MAXC * JSPLIT * MAXN];   // per-chunk argmin (abs target idx)
__device__ float g_nd2_part[MAXC];
__device__ float g_opp_part[MAXC];
__device__ float g_occ_part[2 * MAXP];
__device__ float g_sf_part [2 * MAXP];
__device__ unsigned int g_ctr;                   // zero-init; wraps each launch

__device__ __forceinline__ void block_reduce2(float& a, float& b,
                                              float* sA, float* sB) {
    const int lane = threadIdx.x & 31;
    const int wid  = threadIdx.x >> 5;
    #pragma unroll
    for (int off = 16; off > 0; off >>= 1) {
        a += __shfl_down_sync(0xffffffffu, a, off);
        b += __shfl_down_sync(0xffffffffu, b, off);
    }
    if (lane == 0) { sA[wid] = a; sB[wid] = b; }
    __syncthreads();
    if (threadIdx.x == 0) {
        const int nw = (blockDim.x + 31) >> 5;
        float ra = 0.f, rb = 0.f;
        for (int w = 0; w < nw; w++) { ra += sA[w]; rb += sB[w]; }
        a = ra; b = rb;
    }
}

// ---------------------------------------------------------------------------
// Pass 1: per-(combo, 256-point block, 256-target chunk) partial NN.
// 128 threads, 2 source points/thread. Chunk staged in SMEM as float4
// (x,y,z,|a|^2); d2 = |a|^2 - 2 w.a + |w|^2. 768 KNN blocks -> ~6 warps/SMSP.
// Extras rows (blockIdx.y >= KC): occlusion + static-flow partial sums.
// ---------------------------------------------------------------------------
__global__ void __launch_bounds__(128) chunk_kernel(
    const float* __restrict__ pc0, const float* __restrict__ pc1,
    const float* __restrict__ ffw, const float* __restrict__ fbw,
    const float* __restrict__ dfw, const float* __restrict__ dbw,
    const float* __restrict__ trfw, const float* __restrict__ trbw,
    const float* __restrict__ stfw, const float* __restrict__ stbw,
    int B, int N, int T)
{
    const int KC = 2 * T * B;
    const int combo = blockIdx.y;
    extern __shared__ float4 sm4[];
    __shared__ float sA[32], sB[32];

    if (combo < KC) {
        const int b   = combo % B;
        const int t   = (combo / B) % T;
        const int dir = combo / (B * T);
        const int chunk = (N + JSPLIT - 1) / JSPLIT;
        const int xb = blockIdx.x / JSPLIT;
        const int jc = blockIdx.x % JSPLIT;
        const int j0 = jc * chunk;
        const int cnt = min(chunk, N - j0);
        if (cnt <= 0) return;

        const float* src_pc = (dir == 0) ? pc0 : pc1;
        const float* tgt_pc = (dir == 0) ? pc1 : pc0;
        const float* src_fl = (dir == 0) ? ffw : fbw;
        src_pc += (size_t)b * N * 3;
        tgt_pc += (size_t)b * N * 3;
        src_fl += ((size_t)t * B + b) * (size_t)N * 3;

        for (int i = threadIdx.x; i < cnt; i += 128) {
            const float ax = tgt_pc[(j0 + i) * 3 + 0];
            const float ay = tgt_pc[(j0 + i) * 3 + 1];
            const float az = tgt_pc[(j0 + i) * 3 + 2];
            sm4[i] = make_float4(ax, ay, az, fmaf(ax, ax, fmaf(ay, ay, az * az)));
        }
        __syncthreads();

        const int n0 = xb * 256 + (int)threadIdx.x;
        const int n1 = n0 + 128;
        const bool v0 = (n0 < N);
        const bool v1 = (n1 < N);

        float w0x = 0.f, w0y = 0.f, w0z = 0.f, w20 = 0.f;
        float w1x = 0.f, w1y = 0.f, w1z = 0.f, w21 = 0.f;
        if (v0) {
            w0x = src_pc[n0 * 3 + 0] + src_fl[n0 * 3 + 0];
            w0y = src_pc[n0 * 3 + 1] + src_fl[n0 * 3 + 1];
            w0z = src_pc[n0 * 3 + 2] + src_fl[n0 * 3 + 2];
            w20 = fmaf(w0x, w0x, fmaf(w0y, w0y, w0z * w0z));
        }
        if (v1) {
            w1x = src_pc[n1 * 3 + 0] + src_fl[n1 * 3 + 0];
            w1y = src_pc[n1 * 3 + 1] + src_fl[n1 * 3 + 1];
            w1z = src_pc[n1 * 3 + 2] + src_fl[n1 * 3 + 2];
            w21 = fmaf(w1x, w1x, fmaf(w1y, w1y, w1z * w1z));
        }

        float best0 = 3.402823466e+38f, best1 = 3.402823466e+38f;
        int   bi0 = 0, bi1 = 0;

        if (t == 0) {
            #pragma unroll 4
            for (int j = 0; j < cnt; j++) {
                const float4 a = sm4[j];
                const float s0 = fmaf(fmaf(a.x, w0x, fmaf(a.y, w0y, a.z * w0z)), -2.f, a.w);
                if (s0 < best0) { best0 = s0; bi0 = j; }
                const float s1 = fmaf(fmaf(a.x, w1x, fmaf(a.y, w1y, a.z * w1z)), -2.f, a.w);
                if (s1 < best1) { best1 = s1; bi1 = j; }
            }
        } else {
            #pragma unroll 8
            for (int j = 0; j < cnt; j++) {
                const float4 a = sm4[j];
                const float c0 = fmaf(a.x, w0x, fmaf(a.y, w0y, a.z * w0z));
                const float c1 = fmaf(a.x, w1x, fmaf(a.y, w1y, a.z * w1z));
                best0 = fminf(best0, fmaf(c0, -2.f, a.w));
                best1 = fminf(best1, fmaf(c1, -2.f, a.w));
            }
        }

        float* bb = g_best + ((size_t)combo * JSPLIT + jc) * N;
        int*   ii = g_bidx + ((size_t)combo * JSPLIT + jc) * N;
        if (v0) { bb[n0] = best0 + w20; if (t == 0) ii[n0] = j0 + bi0; }
        if (v1) { bb[n1] = best1 + w21; if (t == 0) ii[n1] = j0 + bi1; }
    } else {
        // extras: occlusion + static-flow partials
        const int dir = combo - KC;
        const float* pc  = (dir == 0) ? pc0  : pc1;
        const float* fl  = (dir == 0) ? ffw  : fbw;
        const float* dis = (dir == 0) ? dfw  : dbw;
        const float* st  = (dir == 0) ? stfw : stbw;
        const float* trg = (dir == 0) ? trfw : trbw;
        const int BN = B * N;
        fl += (size_t)2 * BN * 3;

        float occ = 0.f, sf = 0.f;
        for (int i = blockIdx.x * 128 + (int)threadIdx.x; i < BN;
             i += gridDim.x * 128) {
            occ += dis[i];
            const int b = i / N;
            const float* m = trg + (size_t)b * 16;
            const float px = pc[i * 3 + 0], py = pc[i * 3 + 1], pz = pc[i * 3 + 2];
            const float ix = fmaf(m[0], px, fmaf(m[1],  py, fmaf(m[2],  pz, m[3])))  - px;
            const float iy = fmaf(m[4], px, fmaf(m[5],  py, fmaf(m[6],  pz, m[7])))  - py;
            const float iz = fmaf(m[8], px, fmaf(m[9],  py, fmaf(m[10], pz, m[11]))) - pz;
            const float* f = fl + (size_t)i * 3;
            const float dx = f[0] - ix, dy = f[1] - iy, dz = f[2] - iz;
            sf += st[i] * fmaf(dx, dx, fmaf(dy, dy, dz * dz));
        }
        block_reduce2(occ, sf, sA, sB);
        if (threadIdx.x == 0) {
            g_occ_part[dir * gridDim.x + blockIdx.x] = occ;
            g_sf_part [dir * gridDim.x + blockIdx.x] = sf;
        }
    }
}

// ---------------------------------------------------------------------------
// Pass 2: one block per combo (1024 threads). Min over JSPLIT chunks per
// point (first-occurrence ties), nd2/opp block sums; last-arriving block
// folds all partials + extras + trafo loss -> out[0].
// ---------------------------------------------------------------------------
__global__ void __launch_bounds__(1024) combine_kernel(
    const float* __restrict__ ffw, const float* __restrict__ fbw,
    const float* __restrict__ trfw, const float* __restrict__ trbw,
    float* __restrict__ out, int B, int N, int T, int nbx1)
{
    const int combo = blockIdx.x;
    const int b   = combo % B;
    const int t   = (combo / B) % T;
    const int dir = combo / (B * T);
    const int KC  = 2 * T * B;
    const int tid = threadIdx.x;
    __shared__ float sA[32], sB[32];
    __shared__ bool isLast;

    float v_nd2 = 0.f, v_opp = 0.f;
    const float* bb = g_best + (size_t)combo * JSPLIT * N;
    for (int n = tid; n < N; n += 1024) {
        float best = bb[n];
        int   jcb  = 0;
        #pragma unroll
        for (int jc = 1; jc < JSPLIT; jc++) {
            const float v = bb[(size_t)jc * N + n];
            if (v < best) { best = v; jcb = jc; }
        }
        v_nd2 += fmaxf(best, 0.f);
        if (t == 0) {
            const int idx = g_bidx[((size_t)combo * JSPLIT + jcb) * N + n];
            const float* src_fl = ((dir == 0) ? ffw : fbw) + ((size_t)t * B + b) * (size_t)N * 3;
            const float* tgt_fl = ((dir == 0) ? fbw : ffw) + ((size_t)t * B + b) * (size_t)N * 3;
            const float ox = src_fl[n * 3 + 0] + tgt_fl[idx * 3 + 0];
            const float oy = src_fl[n * 3 + 1] + tgt_fl[idx * 3 + 1];
            const float oz = src_fl[n * 3 + 2] + tgt_fl[idx * 3 + 2];
            v_opp += fmaf(ox, ox, fmaf(oy, oy, oz * oz));
        }
    }

    block_reduce2(v_nd2, v_opp, sA, sB);
    if (tid == 0) {
        g_nd2_part[combo] = v_nd2;
        g_opp_part[combo] = v_opp;
        __threadfence();
        const unsigned old = atomicInc(&g_ctr, (unsigned)KC - 1);  // wraps
        isLast = (old == (unsigned)KC - 1);
    }
    __syncthreads();
    if (!isLast) return;

    // ---- final fold (one block) ----
    const int BN = B * N;
    float accA = 0.f, accB = 0.f;
    for (int c = tid; c < KC; c += 1024) {
        const int tt = (c / B) % T;
        const float wnd = (tt == 0) ? 0.5f : 0.25f;   // knn pens * 0.5 fw/bw
        float v = wnd * g_nd2_part[c];
        if (tt == 0) v += 0.5f * g_opp_part[c];
        accA += v;
    }
    for (int i = tid; i < 2 * nbx1; i += 1024) {
        accA += 0.05f * g_occ_part[i] + 0.5f * g_sf_part[i];
    }
    for (int e = tid; e < B * 16; e += 1024) {
        const int bbq = e >> 4, r = (e >> 2) & 3, k = e & 3;
        const float* A  = trfw + (size_t)bbq * 16;
        const float* Bm = trbw + (size_t)bbq * 16;
        float c = 0.f;
        #pragma unroll
        for (int j = 0; j < 4; j++) c = fmaf(A[r * 4 + j], Bm[j * 4 + k], c);
        const float d = c - ((r == k) ? 1.f : 0.f);
        accB += d * d;
    }
    __syncthreads();
    block_reduce2(accA, accB, sA, sB);
    if (tid == 0) out[0] = accA / (float)BN + accB / (float)B;
}

extern "C" void kernel_launch(void* const* d_in, const int* in_sizes, int n_in,
                              void* d_out, int out_size)
{
    const float* pc0  = (const float*)d_in[0];
    const float* pc1  = (const float*)d_in[1];
    const float* ffw  = (const float*)d_in[2];
    const float* fbw  = (const float*)d_in[3];
    const float* dfw  = (const float*)d_in[4];
    const float* dbw  = (const float*)d_in[5];
    const float* trfw = (const float*)d_in[6];
    const float* trbw = (const float*)d_in[7];
    const float* stfw = (const float*)d_in[8];
    const float* stbw = (const float*)d_in[9];
    float* out = (float*)d_out;

    const int B = in_sizes[6] / 16;                 // trafo_fw = [B,4,4]
    const int N = in_sizes[0] / (3 * B);            // pc0 = [B,N,3]
    const int T = in_sizes[2] / (3 * B * N);        // flows_fw = [T,B,N,3]

    const int KC  = 2 * T * B;
    const int nbx = (N + 255) / 256;                // 256 source points / block
    const int chunk = (N + JSPLIT - 1) / JSPLIT;

    dim3 grid1(nbx * JSPLIT, KC + 2);
    const size_t smem = (size_t)chunk * sizeof(float4);   // 4KB at N=2048
    chunk_kernel<<<grid1, 128, smem>>>(pc0, pc1, ffw, fbw, dfw, dbw,
                                       trfw, trbw, stfw, stbw, B, N, T);

    combine_kernel<<<KC, 1024>>>(ffw, fbw, trfw, trbw, out,
                                 B, N, T, nbx * JSPLIT);
}

// round 7
// speedup vs baseline: 1.0708x; 1.0708x over previous
#include <cuda_runtime.h>
#include <cuda_bf16.h>
#include <cstddef>

#define MAXC   16     // max combos (2*T*B <= 12 here)
#define JSPLIT 8      // target-dimension split
#define MAXN   4096   // max points
#define MAXP   128    // max partial blocks per row

// Packed per-point winner: ~(((u64)mono(d2) << 32) | idx), combined with
// atomicMax (no-return -> REDG). 0 = "empty"; readers reset to 0 -> replay-safe.
__device__ unsigned long long g_slot[MAXC * MAXN];
__device__ float g_nd2_part[MAXC * MAXP];
__device__ float g_opp_part[MAXC * MAXP];
__device__ float g_occ_part[2 * MAXP];
__device__ float g_sf_part [2 * MAXP];
__device__ unsigned int g_ctr;                   // zero-init; wraps each launch

__device__ __forceinline__ unsigned int fkey(float f) {
    const unsigned int u = __float_as_uint(f);
    return u ^ ((u & 0x80000000u) ? 0xFFFFFFFFu : 0x80000000u);
}
__device__ __forceinline__ float fkey_inv(unsigned int k) {
    const unsigned int u = (k & 0x80000000u) ? (k ^ 0x80000000u) : ~k;
    return __uint_as_float(u);
}

__device__ __forceinline__ void block_reduce2(float& a, float& b,
                                              float* sA, float* sB) {
    const int lane = threadIdx.x & 31;
    const int wid  = threadIdx.x >> 5;
    #pragma unroll
    for (int off = 16; off > 0; off >>= 1) {
        a += __shfl_down_sync(0xffffffffu, a, off);
        b += __shfl_down_sync(0xffffffffu, b, off);
    }
    if (lane == 0) { sA[wid] = a; sB[wid] = b; }
    __syncthreads();
    if (threadIdx.x == 0) {
        const int nw = (blockDim.x + 31) >> 5;
        float ra = 0.f, rb = 0.f;
        for (int w = 0; w < nw; w++) { ra += sA[w]; rb += sB[w]; }
        a = ra; b = rb;
    }
}

// ---------------------------------------------------------------------------
// Pass 1: per-(combo, 256-pt block, 256-target chunk) partial NN; winner is
// folded across chunks with packed-key atomicMax. Extras rows: occlusion +
// static-flow partial sums.
// ---------------------------------------------------------------------------
__global__ void __launch_bounds__(128) chunk_kernel(
    const float* __restrict__ pc0, const float* __restrict__ pc1,
    const float* __restrict__ ffw, const float* __restrict__ fbw,
    const float* __restrict__ dfw, const float* __restrict__ dbw,
    const float* __restrict__ trfw, const float* __restrict__ trbw,
    const float* __restrict__ stfw, const float* __restrict__ stbw,
    int B, int N, int T)
{
    const int KC = 2 * T * B;
    const int combo = blockIdx.y;
    extern __shared__ float4 sm4[];
    __shared__ float sA[8], sB[8];

    if (combo < KC) {
        const int b   = combo % B;
        const int t   = (combo / B) % T;
        const int dir = combo / (B * T);
        const int chunk = (N + JSPLIT - 1) / JSPLIT;
        const int xb = blockIdx.x / JSPLIT;
        const int jc = blockIdx.x % JSPLIT;
        const int j0 = jc * chunk;
        const int cnt = min(chunk, N - j0);
        if (cnt <= 0) return;

        const float* src_pc = (dir == 0) ? pc0 : pc1;
        const float* tgt_pc = (dir == 0) ? pc1 : pc0;
        const float* src_fl = (dir == 0) ? ffw : fbw;
        src_pc += (size_t)b * N * 3;
        tgt_pc += (size_t)b * N * 3;
        src_fl += ((size_t)t * B + b) * (size_t)N * 3;

        for (int i = threadIdx.x; i < cnt; i += 128) {
            const float ax = tgt_pc[(j0 + i) * 3 + 0];
            const float ay = tgt_pc[(j0 + i) * 3 + 1];
            const float az = tgt_pc[(j0 + i) * 3 + 2];
            sm4[i] = make_float4(ax, ay, az, fmaf(ax, ax, fmaf(ay, ay, az * az)));
        }
        __syncthreads();

        const int n0 = xb * 256 + (int)threadIdx.x;
        const int n1 = n0 + 128;
        const bool v0 = (n0 < N);
        const bool v1 = (n1 < N);

        float w0x = 0.f, w0y = 0.f, w0z = 0.f, w20 = 0.f;
        float w1x = 0.f, w1y = 0.f, w1z = 0.f, w21 = 0.f;
        if (v0) {
            w0x = src_pc[n0 * 3 + 0] + src_fl[n0 * 3 + 0];
            w0y = src_pc[n0 * 3 + 1] + src_fl[n0 * 3 + 1];
            w0z = src_pc[n0 * 3 + 2] + src_fl[n0 * 3 + 2];
            w20 = fmaf(w0x, w0x, fmaf(w0y, w0y, w0z * w0z));
        }
        if (v1) {
            w1x = src_pc[n1 * 3 + 0] + src_fl[n1 * 3 + 0];
            w1y = src_pc[n1 * 3 + 1] + src_fl[n1 * 3 + 1];
            w1z = src_pc[n1 * 3 + 2] + src_fl[n1 * 3 + 2];
            w21 = fmaf(w1x, w1x, fmaf(w1y, w1y, w1z * w1z));
        }

        float best0 = 3.402823466e+38f, best1 = 3.402823466e+38f;
        int   bi0 = 0, bi1 = 0;

        if (t == 0) {
            #pragma unroll 4
            for (int j = 0; j < cnt; j++) {
                const float4 a = sm4[j];
                const float s0 = fmaf(fmaf(a.x, w0x, fmaf(a.y, w0y, a.z * w0z)), -2.f, a.w);
                if (s0 < best0) { best0 = s0; bi0 = j; }
                const float s1 = fmaf(fmaf(a.x, w1x, fmaf(a.y, w1y, a.z * w1z)), -2.f, a.w);
                if (s1 < best1) { best1 = s1; bi1 = j; }
            }
        } else {
            #pragma unroll 8
            for (int j = 0; j < cnt; j++) {
                const float4 a = sm4[j];
                const float c0 = fmaf(a.x, w0x, fmaf(a.y, w0y, a.z * w0z));
                const float c1 = fmaf(a.x, w1x, fmaf(a.y, w1y, a.z * w1z));
                best0 = fminf(best0, fmaf(c0, -2.f, a.w));
                best1 = fminf(best1, fmaf(c1, -2.f, a.w));
            }
        }

        unsigned long long* slot = g_slot + (size_t)combo * N;
        if (v0) {
            const unsigned long long key =
                ((unsigned long long)fkey(best0 + w20) << 32) | (unsigned int)(j0 + bi0);
            atomicMax(slot + n0, ~key);
        }
        if (v1) {
            const unsigned long long key =
                ((unsigned long long)fkey(best1 + w21) << 32) | (unsigned int)(j0 + bi1);
            atomicMax(slot + n1, ~key);
        }
    } else {
        // extras: occlusion + static-flow partials
        const int dir = combo - KC;
        const float* pc  = (dir == 0) ? pc0  : pc1;
        const float* fl  = (dir == 0) ? ffw  : fbw;
        const float* dis = (dir == 0) ? dfw  : dbw;
        const float* st  = (dir == 0) ? stfw : stbw;
        const float* trg = (dir == 0) ? trfw : trbw;
        const int BN = B * N;
        fl += (size_t)2 * BN * 3;

        float occ = 0.f, sf = 0.f;
        for (int i = blockIdx.x * 128 + (int)threadIdx.x; i < BN;
             i += gridDim.x * 128) {
            occ += dis[i];
            const int b = i / N;
            const float* m = trg + (size_t)b * 16;
            const float px = pc[i * 3 + 0], py = pc[i * 3 + 1], pz = pc[i * 3 + 2];
            const float ix = fmaf(m[0], px, fmaf(m[1],  py, fmaf(m[2],  pz, m[3])))  - px;
            const float iy = fmaf(m[4], px, fmaf(m[5],  py, fmaf(m[6],  pz, m[7])))  - py;
            const float iz = fmaf(m[8], px, fmaf(m[9],  py, fmaf(m[10], pz, m[11]))) - pz;
            const float* f = fl + (size_t)i * 3;
            const float dx = f[0] - ix, dy = f[1] - iy, dz = f[2] - iz;
            sf += st[i] * fmaf(dx, dx, fmaf(dy, dy, dz * dz));
        }
        block_reduce2(occ, sf, sA, sB);
        if (threadIdx.x == 0) {
            g_occ_part[dir * gridDim.x + blockIdx.x] = occ;
            g_sf_part [dir * gridDim.x + blockIdx.x] = sf;
        }
    }
}

// ---------------------------------------------------------------------------
// Pass 2: one thread per point. Decode packed winner (reset slot to 0 for the
// next graph replay), opp gather for t==0, block-reduce; last-arriving block
// folds partials + extras + trafo loss -> out[0].
// ---------------------------------------------------------------------------
__global__ void __launch_bounds__(256) combine_kernel(
    const float* __restrict__ ffw, const float* __restrict__ fbw,
    const float* __restrict__ trfw, const float* __restrict__ trbw,
    float* __restrict__ out, int B, int N, int T, int nbx1)
{
    const int combo = blockIdx.y;
    const int b   = combo % B;
    const int t   = (combo / B) % T;
    const int dir = combo / (B * T);
    const int KC  = 2 * T * B;
    const int tid = threadIdx.x;
    __shared__ float sA[8], sB[8];
    __shared__ bool isLast;

    const int n = blockIdx.x * 256 + tid;
    float v_nd2 = 0.f, v_opp = 0.f;
    if (n < N) {
        unsigned long long* slot = g_slot + (size_t)combo * N + n;
        const unsigned long long key = ~(*slot);
        *slot = 0ULL;                                   // reset for next replay
        const float d2 = fkey_inv((unsigned int)(key >> 32));
        v_nd2 = fmaxf(d2, 0.f);
        if (t == 0) {
            const int idx = (int)(unsigned int)(key & 0xFFFFFFFFu);
            const float* src_fl = ((dir == 0) ? ffw : fbw) + ((size_t)t * B + b) * (size_t)N * 3;
            const float* tgt_fl = ((dir == 0) ? fbw : ffw) + ((size_t)t * B + b) * (size_t)N * 3;
            const float ox = src_fl[n * 3 + 0] + tgt_fl[idx * 3 + 0];
            const float oy = src_fl[n * 3 + 1] + tgt_fl[idx * 3 + 1];
            const float oz = src_fl[n * 3 + 2] + tgt_fl[idx * 3 + 2];
            v_opp = fmaf(ox, ox, fmaf(oy, oy, oz * oz));
        }
    }

    block_reduce2(v_nd2, v_opp, sA, sB);
    if (tid == 0) {
        g_nd2_part[combo * gridDim.x + blockIdx.x] = v_nd2;
        g_opp_part[combo * gridDim.x + blockIdx.x] = v_opp;
        __threadfence();
        const unsigned total = gridDim.x * gridDim.y;
        const unsigned old = atomicInc(&g_ctr, total - 1);   // wraps -> replay-safe
        isLast = (old == total - 1);
    }
    __syncthreads();
    if (!isLast) return;

    // ---- final fold (one block, 256 threads) ----
    const int BN = B * N;
    const int nbx2 = gridDim.x;
    float accA = 0.f, accB = 0.f;
    for (int i = tid; i < KC * nbx2; i += 256) {
        const int c  = i / nbx2;
        const int tt = (c / B) % T;
        const float wnd = (tt == 0) ? 0.5f : 0.25f;   // knn pens * 0.5 fw/bw avg
        float v = wnd * g_nd2_part[i];
        if (tt == 0) v += 0.5f * g_opp_part[i];
        accA += v;
    }
    for (int i = tid; i < 2 * nbx1; i += 256) {
        accA += 0.05f * g_occ_part[i] + 0.5f * g_sf_part[i];
    }
    for (int e = tid; e < B * 16; e += 256) {
        const int bbq = e >> 4, r = (e >> 2) & 3, k = e & 3;
        const float* A  = trfw + (size_t)bbq * 16;
        const float* Bm = trbw + (size_t)bbq * 16;
        float c = 0.f;
        #pragma unroll
        for (int j = 0; j < 4; j++) c = fmaf(A[r * 4 + j], Bm[j * 4 + k], c);
        const float d = c - ((r == k) ? 1.f : 0.f);
        accB += d * d;
    }
    __syncthreads();
    block_reduce2(accA, accB, sA, sB);
    if (tid == 0) out[0] = accA / (float)BN + accB / (float)B;
}

extern "C" void kernel_launch(void* const* d_in, const int* in_sizes, int n_in,
                              void* d_out, int out_size)
{
    const float* pc0  = (const float*)d_in[0];
    const float* pc1  = (const float*)d_in[1];
    const float* ffw  = (const float*)d_in[2];
    const float* fbw  = (const float*)d_in[3];
    const float* dfw  = (const float*)d_in[4];
    const float* dbw  = (const float*)d_in[5];
    const float* trfw = (const float*)d_in[6];
    const float* trbw = (const float*)d_in[7];
    const float* stfw = (const float*)d_in[8];
    const float* stbw = (const float*)d_in[9];
    float* out = (float*)d_out;

    const int B = in_sizes[6] / 16;                 // trafo_fw = [B,4,4]
    const int N = in_sizes[0] / (3 * B);            // pc0 = [B,N,3]
    const int T = in_sizes[2] / (3 * B * N);        // flows_fw = [T,B,N,3]

    const int KC  = 2 * T * B;
    const int nbx = (N + 255) / 256;                // 256 source points / block
    const int chunk = (N + JSPLIT - 1) / JSPLIT;

    dim3 grid1(nbx * JSPLIT, KC + 2);
    const size_t smem = (size_t)chunk * sizeof(float4);   // 4KB at N=2048
    chunk_kernel<<<grid1, 128, smem>>>(pc0, pc1, ffw, fbw, dfw, dbw,
                                       trfw, trbw, stfw, stbw, B, N, T);

    dim3 grid2((N + 255) / 256, KC);
    combine_kernel<<<grid2, 256>>>(ffw, fbw, trfw, trbw, out,
                                   B, N, T, nbx * JSPLIT);
}